// round 6
// baseline (speedup 1.0000x reference)
#include <cuda_runtime.h>
#include <cstdint>
#include <cstddef>

#define T_STEPS 32768
#define CD 512
#define ID 1024
#define NG 2048
#define NB   64
#define TPB  256
#define JPB  8            // h indices per CTA
#define NROWS 32          // 4 gates * JPB rows per CTA
#define KW   16           // ulonglong2 (4 floats) chunks per lane

// ---------------- device-global scratch ------------------------------------
__device__ float g_gx[(size_t)T_STEPS * NG];          // precomputed Wx@x + b, [T][2048]
// Private per-consumer replicated h inboxes: [buf][consumer CTA][word]
// word = (h float bits) | (step tag << 32). Exactly ONE poller per address.
__device__ unsigned long long g_hrep[2][NB][CD];

// ---------------- morally-strong relaxed 8B accessors + fence ---------------
__device__ __forceinline__ unsigned long long ld_relax64(const unsigned long long* p) {
    unsigned long long v;
    asm volatile("ld.relaxed.gpu.global.b64 %0, [%1];" : "=l"(v) : "l"(p) : "memory");
    return v;
}
__device__ __forceinline__ void st_relax64(unsigned long long* p, unsigned long long v) {
    asm volatile("st.relaxed.gpu.global.b64 [%0], %1;" :: "l"(p), "l"(v) : "memory");
}
__device__ __forceinline__ void fence_gpu() {
    asm volatile("fence.acq_rel.gpu;" ::: "memory");
}

// ---------------- init (reset all inbox tags every replay) ------------------
__global__ void init_kernel() {
    size_t i = (size_t)blockIdx.x * blockDim.x + threadIdx.x;
    unsigned long long* p = &g_hrep[0][0][0];
    size_t n = (size_t)2 * NB * CD;
    for (size_t k = i; k < n; k += (size_t)gridDim.x * blockDim.x) p[k] = 0ull;
}

// ---------------- GEMM: g_gx[t][r] = sum_k x[t][k]*W[r][k] + b[r] -----------
#define GBM 128
#define GBN 128
#define GBK 8

__global__ __launch_bounds__(256) void gemm_gx_kernel(
    const float* __restrict__ x,
    const float* __restrict__ wf_w, const float* __restrict__ wf_b,
    const float* __restrict__ wi_w, const float* __restrict__ wi_b,
    const float* __restrict__ wc_w, const float* __restrict__ wc_b,
    const float* __restrict__ wo_w, const float* __restrict__ wo_b)
{
    __shared__ float As[GBK][GBM];
    __shared__ float Bs[GBK][GBN];

    const int tid = threadIdx.x;
    const int tx = tid & 15;
    const int ty = tid >> 4;
    const int r0 = blockIdx.x * GBN;
    const int t0 = blockIdx.y * GBM;
    const int gate = r0 >> 9;
    const int rbase = r0 & 511;

    const float* wsrc = (gate == 0) ? wf_w : (gate == 1) ? wi_w : (gate == 2) ? wc_w : wo_w;
    const float* bsrc = (gate == 0) ? wf_b : (gate == 1) ? wi_b : (gate == 2) ? wc_b : wo_b;

    const int lrow = tid >> 1;
    const int lk4  = (tid & 1) * 4;

    float acc[8][8];
    #pragma unroll
    for (int i = 0; i < 8; i++)
        #pragma unroll
        for (int j = 0; j < 8; j++) acc[i][j] = 0.0f;

    for (int k0 = 0; k0 < CD; k0 += GBK) {
        float4 av = *(const float4*)(x    + (size_t)(t0 + lrow) * CD + k0 + lk4);
        float4 bv = *(const float4*)(wsrc + (size_t)(rbase + lrow) * ID + k0 + lk4);
        __syncthreads();
        As[lk4 + 0][lrow] = av.x; As[lk4 + 1][lrow] = av.y;
        As[lk4 + 2][lrow] = av.z; As[lk4 + 3][lrow] = av.w;
        Bs[lk4 + 0][lrow] = bv.x; Bs[lk4 + 1][lrow] = bv.y;
        Bs[lk4 + 2][lrow] = bv.z; Bs[lk4 + 3][lrow] = bv.w;
        __syncthreads();
        #pragma unroll
        for (int k = 0; k < GBK; k++) {
            const float4* As4 = (const float4*)As[k];
            const float4* Bs4 = (const float4*)Bs[k];
            float4 a0 = As4[ty], a1 = As4[16 + ty];
            float4 b0 = Bs4[tx], b1 = Bs4[16 + tx];
            float ar[8] = {a0.x, a0.y, a0.z, a0.w, a1.x, a1.y, a1.z, a1.w};
            float br[8] = {b0.x, b0.y, b0.z, b0.w, b1.x, b1.y, b1.z, b1.w};
            #pragma unroll
            for (int i = 0; i < 8; i++)
                #pragma unroll
                for (int j = 0; j < 8; j++) acc[i][j] += ar[i] * br[j];
        }
    }

    float4 bias0 = *(const float4*)(bsrc + rbase + tx * 4);
    float4 bias1 = *(const float4*)(bsrc + rbase + 64 + tx * 4);
    float bb[8] = {bias0.x, bias0.y, bias0.z, bias0.w, bias1.x, bias1.y, bias1.z, bias1.w};

    #pragma unroll
    for (int i = 0; i < 8; i++) {
        int trow = t0 + ((i < 4) ? (ty * 4 + i) : (64 + ty * 4 + i - 4));
        float4 o0, o1;
        o0.x = acc[i][0] + bb[0]; o0.y = acc[i][1] + bb[1];
        o0.z = acc[i][2] + bb[2]; o0.w = acc[i][3] + bb[3];
        o1.x = acc[i][4] + bb[4]; o1.y = acc[i][5] + bb[5];
        o1.z = acc[i][6] + bb[6]; o1.w = acc[i][7] + bb[7];
        *(float4*)(g_gx + (size_t)trow * NG + r0 + tx * 4)      = o0;
        *(float4*)(g_gx + (size_t)trow * NG + r0 + 64 + tx * 4) = o1;
    }
}

// ---------------- persistent recurrent kernel --------------------------------
__device__ __forceinline__ unsigned long long ffma2(
    unsigned long long a, unsigned long long b, unsigned long long c) {
    unsigned long long d;
    asm ("fma.rn.f32x2 %0, %1, %2, %3;" : "=l"(d) : "l"(a), "l"(b), "l"(c));
    return d;
}
__device__ __forceinline__ float2 unpack2(unsigned long long a) {
    float2 r;
    asm ("mov.b64 {%0, %1}, %2;" : "=f"(r.x), "=f"(r.y) : "l"(a));
    return r;
}
__device__ __forceinline__ float sigmoid_f(float x) {
    return __fdividef(1.0f, 1.0f + __expf(-x));
}
__device__ __forceinline__ float tanh_f(float x) {
    float ax = fabsf(x);
    float e  = __expf(-2.0f * ax);
    float t  = __fdividef(1.0f - e, 1.0f + e);
    return copysignf(t, x);
}

__global__ __launch_bounds__(TPB, 1) void lstm_rec_kernel(
    const float* __restrict__ wf_w, const float* __restrict__ wi_w,
    const float* __restrict__ wc_w, const float* __restrict__ wo_w,
    float* __restrict__ d_out)
{
    __shared__ ulonglong2 hs[CD / 4];   // h(t) as f32x2 pairs, 128 x 16B
    __shared__ float gsm[NROWS];        // per-row recurrent dots
    __shared__ float hshare[JPB];       // this CTA's new h values (for relay)

    const int tid  = threadIdx.x;
    const int r    = tid >> 3;          // local row 0..31
    const int c    = tid & 7;           // lane within row
    const int gate = r >> 3;
    const int jj   = r & 7;
    const int cta  = blockIdx.x;
    const int j0   = cta * JPB;

    // ---- this thread's 64 h-part weights in registers (16 x ulonglong2)
    const float* wsrc = (gate == 0) ? wf_w : (gate == 1) ? wi_w : (gate == 2) ? wc_w : wo_w;
    const ulonglong2* wp = (const ulonglong2*)(wsrc + (size_t)(j0 + jj) * ID + CD);
    ulonglong2 wv[KW];
    #pragma unroll
    for (int kk = 0; kk < KW; kk++) wv[kk] = wp[c + 8 * kk];

    // ---- relay destination for this thread: writes our values j, j+1 to inbox cdst
    const int pi   = 2 * tid;           // pair index 0..510
    const int cdst = pi >> 3;           // destination consumer CTA 0..63
    const int jrel = pi & 7;            // which of our 8 values (even)

    // ---- gx (x-part) registers for the JPB owner threads
    const bool owner = (tid < JPB);
    const float* gxp = g_gx + j0 + tid;
    float gxf = 0.f, gxi = 0.f, gxc = 0.f, gxo = 0.f;
    if (owner) {
        gxf = __ldcs(gxp);
        gxi = __ldcs(gxp + CD);
        gxc = __ldcs(gxp + 2 * CD);
        gxo = __ldcs(gxp + 3 * CD);
    }

    float c_state = 0.0f;
    float h_last  = 0.0f;

    unsigned long long* hsll = (unsigned long long*)hs;

    for (int t = 0; t < T_STEPS; t++) {
        // ---- prefetch next step's x-part (flies during the poll)
        float nf = 0.f, ni = 0.f, nc = 0.f, no = 0.f;
        if (owner && (t + 1) < T_STEPS) {
            const float* p = gxp + (size_t)(t + 1) * NG;
            nf = __ldcs(p);
            ni = __ldcs(p + CD);
            nc = __ldcs(p + 2 * CD);
            no = __ldcs(p + 3 * CD);
        }

        // ---- wait for h(t) in OUR private inbox (single poller per address)
        unsigned long long* inbox = &g_hrep[t & 1][cta][0];
        unsigned long long v0 = ld_relax64(inbox + 2 * tid);
        while ((unsigned)(v0 >> 32) != (unsigned)t) v0 = ld_relax64(inbox + 2 * tid);
        unsigned long long v1 = ld_relax64(inbox + 2 * tid + 1);
        while ((unsigned)(v1 >> 32) != (unsigned)t) v1 = ld_relax64(inbox + 2 * tid + 1);
        fence_gpu();   // acquire: order our later reads/writes after these observations
        hsll[tid] = (v0 & 0xffffffffull) | (v1 << 32);   // two packed h floats
        __syncthreads();                                  // bar1

        // ---- recurrent dot: 64 MACs via 32 packed f32x2 FMAs
        unsigned long long a0 = 0ull, a1 = 0ull, a2 = 0ull, a3 = 0ull;
        #pragma unroll
        for (int kk = 0; kk < KW; kk += 2) {
            ulonglong2 h0 = hs[c + 8 * kk];
            ulonglong2 h1 = hs[c + 8 * (kk + 1)];
            a0 = ffma2(wv[kk].x,     h0.x, a0);
            a1 = ffma2(wv[kk].y,     h0.y, a1);
            a2 = ffma2(wv[kk + 1].x, h1.x, a2);
            a3 = ffma2(wv[kk + 1].y, h1.y, a3);
        }
        float2 u0 = unpack2(a0), u1 = unpack2(a1), u2 = unpack2(a2), u3 = unpack2(a3);
        float acc = ((u0.x + u0.y) + (u1.x + u1.y)) + ((u2.x + u2.y) + (u3.x + u3.y));
        acc += __shfl_down_sync(0xffffffffu, acc, 4);
        acc += __shfl_down_sync(0xffffffffu, acc, 2);
        acc += __shfl_down_sync(0xffffffffu, acc, 1);
        if (c == 0) gsm[r] = acc;
        __syncthreads();                                  // bar2

        // ---- gate update (8 owner threads), stash h for relay
        if (owner) {
            float gf = gsm[tid]      + gxf;
            float gi = gsm[ 8 + tid] + gxi;
            float gc = gsm[16 + tid] + gxc;
            float go = gsm[24 + tid] + gxo;
            float f  = sigmoid_f(gf);
            float ii = sigmoid_f(gi);
            float cc = tanh_f(gc);
            float oo = sigmoid_f(go);
            c_state = f * c_state + ii * cc;
            h_last  = tanh_f(c_state) * oo;
            hshare[tid] = h_last;
            gxf = nf; gxi = ni; gxc = nc; gxo = no;
        }
        __syncthreads();                                  // bar3

        // ---- fan-out: every thread relays 2 of our 8 values to one inbox
        {
            unsigned long long tag = ((unsigned long long)(unsigned)(t + 1)) << 32;
            unsigned long long p0 = (unsigned long long)__float_as_uint(hshare[jrel])     | tag;
            unsigned long long p1 = (unsigned long long)__float_as_uint(hshare[jrel + 1]) | tag;
            fence_gpu();   // release: order hshare reads + prior step's loads before publish
            unsigned long long* dst = &g_hrep[(t + 1) & 1][cdst][j0 + jrel];
            st_relax64(dst,     p0);
            st_relax64(dst + 1, p1);
        }
        // next iteration's private poll is the inter-CTA barrier
    }

    if (owner) {
        d_out[j0 + tid]      = c_state;   // output = (c, h)
        d_out[CD + j0 + tid] = h_last;
    }
}

// ---------------- launch -----------------------------------------------------
extern "C" void kernel_launch(void* const* d_in, const int* in_sizes, int n_in,
                              void* d_out, int out_size) {
    (void)in_sizes; (void)n_in; (void)out_size;
    const float* x    = (const float*)d_in[0];
    const float* wf_w = (const float*)d_in[1];
    const float* wf_b = (const float*)d_in[2];
    const float* wi_w = (const float*)d_in[3];
    const float* wi_b = (const float*)d_in[4];
    const float* wc_w = (const float*)d_in[5];
    const float* wc_b = (const float*)d_in[6];
    const float* wo_w = (const float*)d_in[7];
    const float* wo_b = (const float*)d_in[8];
    float* out = (float*)d_out;

    init_kernel<<<64, 256>>>();

    dim3 ggrid(NG / GBN, T_STEPS / GBM);
    gemm_gx_kernel<<<ggrid, 256>>>(x, wf_w, wf_b, wi_w, wi_b, wc_w, wc_b, wo_w, wo_b);

    lstm_rec_kernel<<<NB, TPB>>>(wf_w, wi_w, wc_w, wo_w, out);
}

// round 8
// speedup vs baseline: 1.0564x; 1.0564x over previous
#include <cuda_runtime.h>
#include <cstdint>
#include <cstddef>

#define T_STEPS 32768
#define CD 512
#define ID 1024
#define NG 2048
#define NB   64
#define TPB  256
#define JPB  8            // h indices per CTA
#define NROWS 32          // 4 gates * JPB rows per CTA
#define KW   16           // ulonglong2 (4 floats) chunks per lane
#define FSTRIDE 16        // flag stride in ull (=128B), one L2 line per flag

// ---------------- device-global scratch ------------------------------------
__device__ float g_gx[(size_t)T_STEPS * NG];     // precomputed Wx@x + b, [T][2048]
__device__ float g_hdata[2][NB][JPB];            // published h values (plain data)
__device__ unsigned long long g_hflag[2][NB][FSTRIDE];  // per-producer step flags, 128B apart

// ---------------- morally-strong accessors ----------------------------------
__device__ __forceinline__ unsigned long long ld_acq64(const unsigned long long* p) {
    unsigned long long v;
    asm volatile("ld.acquire.gpu.global.b64 %0, [%1];" : "=l"(v) : "l"(p) : "memory");
    return v;
}
__device__ __forceinline__ void st_rel64(unsigned long long* p, unsigned long long v) {
    asm volatile("st.release.gpu.global.b64 [%0], %1;" :: "l"(p), "l"(v) : "memory");
}

// ---------------- init (reset ALL flags + h(0) every replay) ----------------
__global__ void init_kernel() {
    int i = blockIdx.x * blockDim.x + threadIdx.x;
    if (i < 2 * NB * FSTRIDE) (&g_hflag[0][0][0])[i] = 0ull;   // flag = step 0 ready
    if (i < 2 * NB * JPB) (&g_hdata[0][0][0])[i] = 0.0f;       // h(0) = 0
}

// ---------------- GEMM: g_gx[t][r] = sum_k x[t][k]*W[r][k] + b[r] -----------
#define GBM 128
#define GBN 128
#define GBK 8

__global__ __launch_bounds__(256) void gemm_gx_kernel(
    const float* __restrict__ x,
    const float* __restrict__ wf_w, const float* __restrict__ wf_b,
    const float* __restrict__ wi_w, const float* __restrict__ wi_b,
    const float* __restrict__ wc_w, const float* __restrict__ wc_b,
    const float* __restrict__ wo_w, const float* __restrict__ wo_b)
{
    __shared__ float As[GBK][GBM];
    __shared__ float Bs[GBK][GBN];

    const int tid = threadIdx.x;
    const int tx = tid & 15;
    const int ty = tid >> 4;
    const int r0 = blockIdx.x * GBN;
    const int t0 = blockIdx.y * GBM;
    const int gate = r0 >> 9;
    const int rbase = r0 & 511;

    const float* wsrc = (gate == 0) ? wf_w : (gate == 1) ? wi_w : (gate == 2) ? wc_w : wo_w;
    const float* bsrc = (gate == 0) ? wf_b : (gate == 1) ? wi_b : (gate == 2) ? wc_b : wo_b;

    const int lrow = tid >> 1;
    const int lk4  = (tid & 1) * 4;

    float acc[8][8];
    #pragma unroll
    for (int i = 0; i < 8; i++)
        #pragma unroll
        for (int j = 0; j < 8; j++) acc[i][j] = 0.0f;

    for (int k0 = 0; k0 < CD; k0 += GBK) {
        float4 av = *(const float4*)(x    + (size_t)(t0 + lrow) * CD + k0 + lk4);
        float4 bv = *(const float4*)(wsrc + (size_t)(rbase + lrow) * ID + k0 + lk4);
        __syncthreads();
        As[lk4 + 0][lrow] = av.x; As[lk4 + 1][lrow] = av.y;
        As[lk4 + 2][lrow] = av.z; As[lk4 + 3][lrow] = av.w;
        Bs[lk4 + 0][lrow] = bv.x; Bs[lk4 + 1][lrow] = bv.y;
        Bs[lk4 + 2][lrow] = bv.z; Bs[lk4 + 3][lrow] = bv.w;
        __syncthreads();
        #pragma unroll
        for (int k = 0; k < GBK; k++) {
            const float4* As4 = (const float4*)As[k];
            const float4* Bs4 = (const float4*)Bs[k];
            float4 a0 = As4[ty], a1 = As4[16 + ty];
            float4 b0 = Bs4[tx], b1 = Bs4[16 + tx];
            float ar[8] = {a0.x, a0.y, a0.z, a0.w, a1.x, a1.y, a1.z, a1.w};
            float br[8] = {b0.x, b0.y, b0.z, b0.w, b1.x, b1.y, b1.z, b1.w};
            #pragma unroll
            for (int i = 0; i < 8; i++)
                #pragma unroll
                for (int j = 0; j < 8; j++) acc[i][j] += ar[i] * br[j];
        }
    }

    float4 bias0 = *(const float4*)(bsrc + rbase + tx * 4);
    float4 bias1 = *(const float4*)(bsrc + rbase + 64 + tx * 4);
    float bb[8] = {bias0.x, bias0.y, bias0.z, bias0.w, bias1.x, bias1.y, bias1.z, bias1.w};

    #pragma unroll
    for (int i = 0; i < 8; i++) {
        int trow = t0 + ((i < 4) ? (ty * 4 + i) : (64 + ty * 4 + i - 4));
        float4 o0, o1;
        o0.x = acc[i][0] + bb[0]; o0.y = acc[i][1] + bb[1];
        o0.z = acc[i][2] + bb[2]; o0.w = acc[i][3] + bb[3];
        o1.x = acc[i][4] + bb[4]; o1.y = acc[i][5] + bb[5];
        o1.z = acc[i][6] + bb[6]; o1.w = acc[i][7] + bb[7];
        *(float4*)(g_gx + (size_t)trow * NG + r0 + tx * 4)      = o0;
        *(float4*)(g_gx + (size_t)trow * NG + r0 + 64 + tx * 4) = o1;
    }
}

// ---------------- persistent recurrent kernel --------------------------------
__device__ __forceinline__ unsigned long long ffma2(
    unsigned long long a, unsigned long long b, unsigned long long c) {
    unsigned long long d;
    asm ("fma.rn.f32x2 %0, %1, %2, %3;" : "=l"(d) : "l"(a), "l"(b), "l"(c));
    return d;
}
__device__ __forceinline__ float2 unpack2(unsigned long long a) {
    float2 r;
    asm ("mov.b64 {%0, %1}, %2;" : "=f"(r.x), "=f"(r.y) : "l"(a));
    return r;
}
__device__ __forceinline__ float sigmoid_f(float x) {
    return __fdividef(1.0f, 1.0f + __expf(-x));
}
__device__ __forceinline__ float tanh_f(float x) {
    float ax = fabsf(x);
    float e  = __expf(-2.0f * ax);
    float t  = __fdividef(1.0f - e, 1.0f + e);
    return copysignf(t, x);
}

__global__ __launch_bounds__(TPB, 1) void lstm_rec_kernel(
    const float* __restrict__ wf_w, const float* __restrict__ wi_w,
    const float* __restrict__ wc_w, const float* __restrict__ wo_w,
    float* __restrict__ d_out)
{
    __shared__ __align__(16) float hsf[CD];   // h(t) broadcast
    __shared__ float gsm[NROWS];              // per-row recurrent dots

    const ulonglong2* hs = (const ulonglong2*)hsf;
    float4* hs4 = (float4*)hsf;

    const int tid  = threadIdx.x;
    const int r    = tid >> 3;          // local row 0..31
    const int c    = tid & 7;           // lane within row
    const int gate = r >> 3;
    const int jj   = r & 7;
    const int cta  = blockIdx.x;
    const int j0   = cta * JPB;

    // ---- this thread's 64 h-part weights in registers (16 x ulonglong2)
    const float* wsrc = (gate == 0) ? wf_w : (gate == 1) ? wi_w : (gate == 2) ? wc_w : wo_w;
    const ulonglong2* wp = (const ulonglong2*)(wsrc + (size_t)(j0 + jj) * ID + CD);
    ulonglong2 wv[KW];
    #pragma unroll
    for (int kk = 0; kk < KW; kk++) wv[kk] = wp[c + 8 * kk];

    // ---- gx (x-part) registers for the JPB owner threads
    const bool owner = (tid < JPB);
    const float* gxp = g_gx + j0 + tid;
    float gxf = 0.f, gxi = 0.f, gxc = 0.f, gxo = 0.f;
    if (owner) {
        gxf = __ldcs(gxp);
        gxi = __ldcs(gxp + CD);
        gxc = __ldcs(gxp + 2 * CD);
        gxo = __ldcs(gxp + 3 * CD);
    }

    float c_state = 0.0f;
    float h_last  = 0.0f;

    for (int t = 0; t < T_STEPS; t++) {
        const int b  = t & 1;
        const int b2 = (t + 1) & 1;

        // ---- prefetch next step's x-part (issued before the spin)
        float nf = 0.f, ni = 0.f, nc = 0.f, no = 0.f;
        if (owner && (t + 1) < T_STEPS) {
            const float* p = gxp + (size_t)(t + 1) * NG;
            nf = __ldcs(p);
            ni = __ldcs(p + CD);
            nc = __ldcs(p + 2 * CD);
            no = __ldcs(p + 3 * CD);
        }

        // ---- wait for h(t): only 64 threads spin, one flag (own L2 line) each
        if (tid < NB) {
            const unsigned long long* fp = &g_hflag[b][tid][0];
            unsigned long long v = ld_acq64(fp);
            while ((unsigned)v != (unsigned)t) v = ld_acq64(fp);
        }
        __syncthreads();                                  // bar1: all flags seen

        // ---- one-shot wide gather of h(t) (weak .cv loads, ordered by acq+bar)
        if (tid < CD / 4) {
            const float4* src = (const float4*)&g_hdata[b][tid >> 1][(tid & 1) * 4];
            hs4[tid] = __ldcv(src);
        }
        __syncthreads();                                  // bar2: h in smem

        // ---- recurrent dot: 64 MACs via 32 packed f32x2 FMAs
        unsigned long long a0 = 0ull, a1 = 0ull, a2 = 0ull, a3 = 0ull;
        #pragma unroll
        for (int kk = 0; kk < KW; kk += 2) {
            ulonglong2 h0 = hs[c + 8 * kk];
            ulonglong2 h1 = hs[c + 8 * (kk + 1)];
            a0 = ffma2(wv[kk].x,     h0.x, a0);
            a1 = ffma2(wv[kk].y,     h0.y, a1);
            a2 = ffma2(wv[kk + 1].x, h1.x, a2);
            a3 = ffma2(wv[kk + 1].y, h1.y, a3);
        }
        float2 u0 = unpack2(a0), u1 = unpack2(a1), u2 = unpack2(a2), u3 = unpack2(a3);
        float acc = ((u0.x + u0.y) + (u1.x + u1.y)) + ((u2.x + u2.y) + (u3.x + u3.y));
        acc += __shfl_down_sync(0xffffffffu, acc, 4);
        acc += __shfl_down_sync(0xffffffffu, acc, 2);
        acc += __shfl_down_sync(0xffffffffu, acc, 1);
        if (c == 0) gsm[r] = acc;
        __syncthreads();                                  // bar3: dots ready

        // ---- gate update (8 owner threads) + data stores
        if (owner) {
            float gf = gsm[tid]      + gxf;
            float gi = gsm[ 8 + tid] + gxi;
            float gc = gsm[16 + tid] + gxc;
            float go = gsm[24 + tid] + gxo;
            float f  = sigmoid_f(gf);
            float ii = sigmoid_f(gi);
            float cc = tanh_f(gc);
            float oo = sigmoid_f(go);
            c_state = f * c_state + ii * cc;
            h_last  = tanh_f(c_state) * oo;
            __stcg(&g_hdata[b2][cta][tid], h_last);        // plain data store
            gxf = nf; gxi = ni; gxc = nc; gxo = no;
        }
        __syncthreads();                                  // bar4: data stores issued
        if (tid == 0)
            st_rel64(&g_hflag[b2][cta][0], (unsigned long long)(unsigned)(t + 1));
        // next iteration's acquire-poll completes the barrier
    }

    if (owner) {
        d_out[j0 + tid]      = c_state;   // output = (c, h)
        d_out[CD + j0 + tid] = h_last;
    }
}

// ---------------- launch -----------------------------------------------------
extern "C" void kernel_launch(void* const* d_in, const int* in_sizes, int n_in,
                              void* d_out, int out_size) {
    (void)in_sizes; (void)n_in; (void)out_size;
    const float* x    = (const float*)d_in[0];
    const float* wf_w = (const float*)d_in[1];
    const float* wf_b = (const float*)d_in[2];
    const float* wi_w = (const float*)d_in[3];
    const float* wi_b = (const float*)d_in[4];
    const float* wc_w = (const float*)d_in[5];
    const float* wc_b = (const float*)d_in[6];
    const float* wo_w = (const float*)d_in[7];
    const float* wo_b = (const float*)d_in[8];
    float* out = (float*)d_out;

    init_kernel<<<2, 1024>>>();

    dim3 ggrid(NG / GBN, T_STEPS / GBM);
    gemm_gx_kernel<<<ggrid, 256>>>(x, wf_w, wf_b, wi_w, wi_b, wc_w, wc_b, wo_w, wo_b);

    lstm_rec_kernel<<<NB, TPB>>>(wf_w, wi_w, wc_w, wo_w, out);
}

// round 9
// speedup vs baseline: 1.1990x; 1.1350x over previous
#include <cuda_runtime.h>
#include <cstdint>
#include <cstddef>

#define T_STEPS 32768
#define CD 512
#define ID 1024
#define NG 2048
#define NB   64
#define TPB  256
#define JPB  8            // h indices per CTA
#define NROWS 32          // 4 gates * JPB rows per CTA
#define KW   16           // ulonglong2 (4 floats) chunks per lane

// ---------------- device-global scratch ------------------------------------
__device__ float g_gx[(size_t)T_STEPS * NG];   // precomputed Wx@x + b, [T][2048]
__device__ float g_hbuf[2][CD];                // double-buffered h (plain data)
__device__ unsigned int g_counter;             // monotonic arrival counter

// ---------------- morally-strong accessors ----------------------------------
__device__ __forceinline__ unsigned int ld_acq32(const unsigned int* p) {
    unsigned int v;
    asm volatile("ld.acquire.gpu.global.u32 %0, [%1];" : "=r"(v) : "l"(p) : "memory");
    return v;
}
__device__ __forceinline__ void red_rel_add(unsigned int* p, unsigned int v) {
    asm volatile("red.release.gpu.global.add.u32 [%0], %1;" :: "l"(p), "r"(v) : "memory");
}

// ---------------- init (reset counter + h(0) every replay) ------------------
__global__ void init_kernel() {
    int i = threadIdx.x;
    if (i < 2 * CD) (&g_hbuf[0][0])[i] = 0.0f;
    if (i == 0) g_counter = 0u;
}

// ---------------- GEMM: g_gx[t][r] = sum_k x[t][k]*W[r][k] + b[r] -----------
#define GBM 128
#define GBN 128
#define GBK 8

__global__ __launch_bounds__(256) void gemm_gx_kernel(
    const float* __restrict__ x,
    const float* __restrict__ wf_w, const float* __restrict__ wf_b,
    const float* __restrict__ wi_w, const float* __restrict__ wi_b,
    const float* __restrict__ wc_w, const float* __restrict__ wc_b,
    const float* __restrict__ wo_w, const float* __restrict__ wo_b)
{
    __shared__ float As[GBK][GBM];
    __shared__ float Bs[GBK][GBN];

    const int tid = threadIdx.x;
    const int tx = tid & 15;
    const int ty = tid >> 4;
    const int r0 = blockIdx.x * GBN;
    const int t0 = blockIdx.y * GBM;
    const int gate = r0 >> 9;
    const int rbase = r0 & 511;

    const float* wsrc = (gate == 0) ? wf_w : (gate == 1) ? wi_w : (gate == 2) ? wc_w : wo_w;
    const float* bsrc = (gate == 0) ? wf_b : (gate == 1) ? wi_b : (gate == 2) ? wc_b : wo_b;

    const int lrow = tid >> 1;
    const int lk4  = (tid & 1) * 4;

    float acc[8][8];
    #pragma unroll
    for (int i = 0; i < 8; i++)
        #pragma unroll
        for (int j = 0; j < 8; j++) acc[i][j] = 0.0f;

    for (int k0 = 0; k0 < CD; k0 += GBK) {
        float4 av = *(const float4*)(x    + (size_t)(t0 + lrow) * CD + k0 + lk4);
        float4 bv = *(const float4*)(wsrc + (size_t)(rbase + lrow) * ID + k0 + lk4);
        __syncthreads();
        As[lk4 + 0][lrow] = av.x; As[lk4 + 1][lrow] = av.y;
        As[lk4 + 2][lrow] = av.z; As[lk4 + 3][lrow] = av.w;
        Bs[lk4 + 0][lrow] = bv.x; Bs[lk4 + 1][lrow] = bv.y;
        Bs[lk4 + 2][lrow] = bv.z; Bs[lk4 + 3][lrow] = bv.w;
        __syncthreads();
        #pragma unroll
        for (int k = 0; k < GBK; k++) {
            const float4* As4 = (const float4*)As[k];
            const float4* Bs4 = (const float4*)Bs[k];
            float4 a0 = As4[ty], a1 = As4[16 + ty];
            float4 b0 = Bs4[tx], b1 = Bs4[16 + tx];
            float ar[8] = {a0.x, a0.y, a0.z, a0.w, a1.x, a1.y, a1.z, a1.w};
            float br[8] = {b0.x, b0.y, b0.z, b0.w, b1.x, b1.y, b1.z, b1.w};
            #pragma unroll
            for (int i = 0; i < 8; i++)
                #pragma unroll
                for (int j = 0; j < 8; j++) acc[i][j] += ar[i] * br[j];
        }
    }

    float4 bias0 = *(const float4*)(bsrc + rbase + tx * 4);
    float4 bias1 = *(const float4*)(bsrc + rbase + 64 + tx * 4);
    float bb[8] = {bias0.x, bias0.y, bias0.z, bias0.w, bias1.x, bias1.y, bias1.z, bias1.w};

    #pragma unroll
    for (int i = 0; i < 8; i++) {
        int trow = t0 + ((i < 4) ? (ty * 4 + i) : (64 + ty * 4 + i - 4));
        float4 o0, o1;
        o0.x = acc[i][0] + bb[0]; o0.y = acc[i][1] + bb[1];
        o0.z = acc[i][2] + bb[2]; o0.w = acc[i][3] + bb[3];
        o1.x = acc[i][4] + bb[4]; o1.y = acc[i][5] + bb[5];
        o1.z = acc[i][6] + bb[6]; o1.w = acc[i][7] + bb[7];
        *(float4*)(g_gx + (size_t)trow * NG + r0 + tx * 4)      = o0;
        *(float4*)(g_gx + (size_t)trow * NG + r0 + 64 + tx * 4) = o1;
    }
}

// ---------------- persistent recurrent kernel --------------------------------
__device__ __forceinline__ unsigned long long ffma2(
    unsigned long long a, unsigned long long b, unsigned long long c) {
    unsigned long long d;
    asm ("fma.rn.f32x2 %0, %1, %2, %3;" : "=l"(d) : "l"(a), "l"(b), "l"(c));
    return d;
}
__device__ __forceinline__ float2 unpack2(unsigned long long a) {
    float2 r;
    asm ("mov.b64 {%0, %1}, %2;" : "=f"(r.x), "=f"(r.y) : "l"(a));
    return r;
}
__device__ __forceinline__ float sigmoid_f(float x) {
    return __fdividef(1.0f, 1.0f + __expf(-x));
}
__device__ __forceinline__ float tanh_f(float x) {
    float ax = fabsf(x);
    float e  = __expf(-2.0f * ax);
    float t  = __fdividef(1.0f - e, 1.0f + e);
    return copysignf(t, x);
}

__global__ __launch_bounds__(TPB, 1) void lstm_rec_kernel(
    const float* __restrict__ wf_w, const float* __restrict__ wi_w,
    const float* __restrict__ wc_w, const float* __restrict__ wo_w,
    float* __restrict__ d_out)
{
    __shared__ __align__(16) float hsf[CD];   // h(t) broadcast
    __shared__ float gsm[NROWS];              // per-row recurrent dots

    const ulonglong2* hs = (const ulonglong2*)hsf;
    float4* hs4 = (float4*)hsf;

    const int tid  = threadIdx.x;
    const int r    = tid >> 3;          // local row 0..31
    const int c    = tid & 7;           // lane within row
    const int gate = r >> 3;
    const int jj   = r & 7;
    const int cta  = blockIdx.x;
    const int j0   = cta * JPB;

    // ---- this thread's 64 h-part weights in registers (16 x ulonglong2)
    const float* wsrc = (gate == 0) ? wf_w : (gate == 1) ? wi_w : (gate == 2) ? wc_w : wo_w;
    const ulonglong2* wp = (const ulonglong2*)(wsrc + (size_t)(j0 + jj) * ID + CD);
    ulonglong2 wv[KW];
    #pragma unroll
    for (int kk = 0; kk < KW; kk++) wv[kk] = wp[c + 8 * kk];

    // ---- gx (x-part) registers for the JPB owner threads
    const bool owner = (tid < JPB);
    const float* gxp = g_gx + j0 + tid;
    float gxf = 0.f, gxi = 0.f, gxc = 0.f, gxo = 0.f;
    if (owner) {
        gxf = __ldcs(gxp);
        gxi = __ldcs(gxp + CD);
        gxc = __ldcs(gxp + 2 * CD);
        gxo = __ldcs(gxp + 3 * CD);
    }

    float c_state = 0.0f;
    float h_last  = 0.0f;

    for (int t = 0; t < T_STEPS; t++) {
        const int b  = t & 1;
        const int b2 = (t + 1) & 1;

        // ---- prefetch next step's x-part (issued before the spin)
        float nf = 0.f, ni = 0.f, nc = 0.f, no = 0.f;
        if (owner && (t + 1) < T_STEPS) {
            const float* p = gxp + (size_t)(t + 1) * NG;
            nf = __ldcs(p);
            ni = __ldcs(p + CD);
            nc = __ldcs(p + 2 * CD);
            no = __ldcs(p + 3 * CD);
        }

        // ---- ONE thread polls the arrival counter (acquire)
        if (tid == 0) {
            unsigned int target = (unsigned int)NB * (unsigned int)t;
            while (ld_acq32(&g_counter) < target) { }
        }
        __syncthreads();                                  // bar1: h(t) published

        // ---- one-shot wide gather of h(t) (.cv, ordered by acquire+bar)
        if (tid < CD / 4) {
            hs4[tid] = __ldcv((const float4*)&g_hbuf[b][4 * tid]);
        }
        __syncthreads();                                  // bar2: h in smem

        // ---- recurrent dot: 64 MACs via 32 packed f32x2 FMAs
        unsigned long long a0 = 0ull, a1 = 0ull, a2 = 0ull, a3 = 0ull;
        #pragma unroll
        for (int kk = 0; kk < KW; kk += 2) {
            ulonglong2 h0 = hs[c + 8 * kk];
            ulonglong2 h1 = hs[c + 8 * (kk + 1)];
            a0 = ffma2(wv[kk].x,     h0.x, a0);
            a1 = ffma2(wv[kk].y,     h0.y, a1);
            a2 = ffma2(wv[kk + 1].x, h1.x, a2);
            a3 = ffma2(wv[kk + 1].y, h1.y, a3);
        }
        float2 u0 = unpack2(a0), u1 = unpack2(a1), u2 = unpack2(a2), u3 = unpack2(a3);
        float acc = ((u0.x + u0.y) + (u1.x + u1.y)) + ((u2.x + u2.y) + (u3.x + u3.y));
        acc += __shfl_down_sync(0xffffffffu, acc, 4);
        acc += __shfl_down_sync(0xffffffffu, acc, 2);
        acc += __shfl_down_sync(0xffffffffu, acc, 1);
        if (c == 0) gsm[r] = acc;
        __syncthreads();                                  // bar3: dots ready

        // ---- gate update (8 owner threads) + data stores
        if (owner) {
            float gf = gsm[tid]      + gxf;
            float gi = gsm[ 8 + tid] + gxi;
            float gc = gsm[16 + tid] + gxc;
            float go = gsm[24 + tid] + gxo;
            float f  = sigmoid_f(gf);
            float ii = sigmoid_f(gi);
            float cc = tanh_f(gc);
            float oo = sigmoid_f(go);
            c_state = f * c_state + ii * cc;
            h_last  = tanh_f(c_state) * oo;
            __stcg(&g_hbuf[b2][j0 + tid], h_last);        // publish h(t+1) data
            gxf = nf; gxi = ni; gxc = nc; gxo = no;
        }
        __syncthreads();                                  // bar4: stores issued
        if (tid == 0)
            red_rel_add(&g_counter, 1u);                  // release arrival
        // next iteration's acquire-poll completes the barrier
    }

    if (owner) {
        d_out[j0 + tid]      = c_state;   // output = (c, h)
        d_out[CD + j0 + tid] = h_last;
    }
}

// ---------------- launch -----------------------------------------------------
extern "C" void kernel_launch(void* const* d_in, const int* in_sizes, int n_in,
                              void* d_out, int out_size) {
    (void)in_sizes; (void)n_in; (void)out_size;
    const float* x    = (const float*)d_in[0];
    const float* wf_w = (const float*)d_in[1];
    const float* wf_b = (const float*)d_in[2];
    const float* wi_w = (const float*)d_in[3];
    const float* wi_b = (const float*)d_in[4];
    const float* wc_w = (const float*)d_in[5];
    const float* wc_b = (const float*)d_in[6];
    const float* wo_w = (const float*)d_in[7];
    const float* wo_b = (const float*)d_in[8];
    float* out = (float*)d_out;

    init_kernel<<<1, 1024>>>();

    dim3 ggrid(NG / GBN, T_STEPS / GBM);
    gemm_gx_kernel<<<ggrid, 256>>>(x, wf_w, wf_b, wi_w, wi_b, wc_w, wc_b, wo_w, wo_b);

    lstm_rec_kernel<<<NB, TPB>>>(wf_w, wi_w, wc_w, wo_w, out);
}